// round 9
// baseline (speedup 1.0000x reference)
#include <cuda_runtime.h>
#include <cuda_bf16.h>

#define N_NODES  100000
#define N_EDGES  1600000
#define N_GRAPHS 512
#define HIDDEN   128
#define CAP      96        // padded CSR; deg ~ Poisson(16), P(>=96) ~ 1e-45
#define SB       68        // smem row stride in uint32 (64 data + 4 pad)
#define NTILES   ((N_NODES + 63) / 64)

// ---------------- scratch (static device globals) ---------------------------
__device__ float4 g_x4 [N_NODES];           // {x0, x1, x2, count->dinv}
__device__ int    g_cnt[N_NODES];           // clamped degree (after k_prep)
__device__ int    g_csr[N_NODES * CAP];     // 38.4 MB padded CSR
__device__ uint2  g_hb [N_NODES * 32];      // h' rows bf16 (25.6 MB)
__device__ uint2  g_gb [N_NODES * 32];      // G  rows bf16 (25.6 MB)
__device__ float  g_gsum[N_GRAPHS];
__device__ int    g_is64;

__device__ __forceinline__ float blo(unsigned w) { return __int_as_float(w << 16); }
__device__ __forceinline__ float bhi(unsigned w) { return __int_as_float(w & 0xffff0000u); }
__device__ __forceinline__ unsigned packbf(float lo, float hi) {
    __nv_bfloat162 p = __float22bfloat162_rn(make_float2(lo, hi));
    return *(const unsigned*)&p;
}
__device__ __forceinline__ unsigned hadd2bf(unsigned a, unsigned b) {
    __nv_bfloat162 r = __hadd2(*(const __nv_bfloat162*)&a, *(const __nv_bfloat162*)&b);
    return *(const unsigned*)&r;
}
__device__ __forceinline__ uint4 hadd2bf4(uint4 a, uint4 b) {
    uint4 r;
    r.x = hadd2bf(a.x, b.x); r.y = hadd2bf(a.y, b.y);
    r.z = hadd2bf(a.z, b.z); r.w = hadd2bf(a.w, b.w);
    return r;
}
__device__ __forceinline__ void acc8(uint4 h, float* a) {
    a[0] += blo(h.x); a[1] += bhi(h.x);
    a[2] += blo(h.y); a[3] += bhi(h.y);
    a[4] += blo(h.z); a[5] += bhi(h.z);
    a[6] += blo(h.w); a[7] += bhi(h.w);
}
__device__ __forceinline__ void mma_bf16(float4& d, unsigned a0, unsigned a1,
                                         unsigned a2, unsigned a3,
                                         unsigned b0, unsigned b1) {
    asm("mma.sync.aligned.m16n8k16.row.col.f32.bf16.bf16.f32 "
        "{%0,%1,%2,%3}, {%4,%5,%6,%7}, {%8,%9}, {%0,%1,%2,%3};"
        : "+f"(d.x), "+f"(d.y), "+f"(d.z), "+f"(d.w)
        : "r"(a0), "r"(a1), "r"(a2), "r"(a3), "r"(b0), "r"(b1));
}

// ---------------- K1: init (x4 with zeroed count, gsum, dtype detect) ---------
__global__ void k_init(const unsigned* __restrict__ ei, const float* __restrict__ x) {
    int i = blockIdx.x * blockDim.x + threadIdx.x;
    if (i == 0) {
        unsigned orv = 0;
#pragma unroll
        for (int t = 1; t < 32; t += 2) orv |= ei[t];   // int64 => high words zero
        g_is64 = (orv == 0u) ? 1 : 0;
    }
    if (i < N_NODES)
        g_x4[i] = make_float4(x[3 * i], x[3 * i + 1], x[3 * i + 2], 0.0f);
    if (i < N_GRAPHS) g_gsum[i] = 0.0f;
}

// ---------------- K2: build padded CSR; counter lives in g_x4[d].w ------------
__global__ void __launch_bounds__(256) k_fill(const void* ei) {
    int e = blockIdx.x * blockDim.x + threadIdx.x;
    if (e >= N_EDGES) return;
    int s, d;
    if (g_is64) {
        s = (int)((const long long*)ei)[e];
        d = (int)((const long long*)ei)[(long long)N_EDGES + e];
    } else {
        s = ((const int*)ei)[e];
        d = ((const int*)ei)[N_EDGES + e];
    }
    int slot = atomicAdd((int*)&g_x4[d].w, 1);
    if (slot < CAP) g_csr[d * CAP + slot] = s;
}

// ---------------- K3: convert count -> dinv, stash clamped degree -------------
__global__ void k_prep() {
    int i = blockIdx.x * blockDim.x + threadIdx.x;
    if (i >= N_NODES) return;
    int c = __float_as_int(g_x4[i].w);
    g_cnt[i] = min(c, CAP);
    g_x4[i].w = rsqrtf((float)(c + 1));
}

// ---------------- K4: fused layer 1 (gather x*dinv + GEMV W1 -> bf16 h') ------
__global__ void __launch_bounds__(256) k_layer1(const float* __restrict__ W1,
                                                const float* __restrict__ b1) {
    int w = threadIdx.x >> 5, lane = threadIdx.x & 31;
    int g = lane >> 2, q = lane & 3;
    int nodeBase = blockIdx.x * 64 + w * 8;
    int nc = min(nodeBase + g, N_NODES - 1);
    float4 xs = g_x4[nc];
    float dd  = xs.w;
    int deg   = g_cnt[nc];
    int start = nc * CAP;

    float px = 0.f, py = 0.f, pz = 0.f;
    for (int j = q; j < deg; j += 4) {
        int s = g_csr[start + j];
        float4 v = __ldg(&g_x4[s]);
        px = fmaf(v.x, v.w, px);
        py = fmaf(v.y, v.w, py);
        pz = fmaf(v.z, v.w, pz);
    }
#pragma unroll
    for (int off = 1; off <= 2; off <<= 1) {
        px += __shfl_xor_sync(0xffffffffu, px, off);
        py += __shfl_xor_sync(0xffffffffu, py, off);
        pz += __shfl_xor_sync(0xffffffffu, pz, off);
    }
    float v0 = dd * (px + xs.x * dd);
    float v1 = dd * (py + xs.y * dd);
    float v2 = dd * (pz + xs.z * dd);

    int c0 = lane << 2;
    const float4 w0 = *(const float4*)&W1[c0];
    const float4 w1 = *(const float4*)&W1[HIDDEN + c0];
    const float4 w2 = *(const float4*)&W1[2 * HIDDEN + c0];
    const float4 bb = *(const float4*)&b1[c0];

#pragma unroll
    for (int r = 0; r < 8; r++) {
        float u0 = __shfl_sync(0xffffffffu, v0, r * 4);
        float u1 = __shfl_sync(0xffffffffu, v1, r * 4);
        float u2 = __shfl_sync(0xffffffffu, v2, r * 4);
        float ud = __shfl_sync(0xffffffffu, dd, r * 4);
        int nd = nodeBase + r;
        if (nd >= N_NODES) break;
        float y0 = fmaf(u0, w0.x, fmaf(u1, w1.x, fmaf(u2, w2.x, bb.x)));
        float y1 = fmaf(u0, w0.y, fmaf(u1, w1.y, fmaf(u2, w2.y, bb.y)));
        float y2 = fmaf(u0, w0.z, fmaf(u1, w1.z, fmaf(u2, w2.z, bb.z)));
        float y3 = fmaf(u0, w0.w, fmaf(u1, w1.w, fmaf(u2, w2.w, bb.w)));
        y0 = fmaxf(y0, 0.f) * ud; y1 = fmaxf(y1, 0.f) * ud;
        y2 = fmaxf(y2, 0.f) * ud; y3 = fmaxf(y3, 0.f) * ud;
        uint2 o;
        o.x = packbf(y0, y1);
        o.y = packbf(y2, y3);
        g_hb[nd * 32 + lane] = o;
    }
}

// ---------------- K5: layer-2 gather — bf16x2 tree accumulation ---------------
__global__ void __launch_bounds__(256) k_gather() {
    int w = threadIdx.x >> 5, lane = threadIdx.x & 31;
    int node = blockIdx.x * 8 + w;
    if (node >= N_NODES) return;
    int deg   = g_cnt[node];
    float dd  = g_x4[node].w;
    int start = node * CAP;
    int half = lane >> 4;        // which edge of the pair this lane serves
    int hl   = lane & 15;        // uint4 slot within the 256-B row

    const uint4* hb4 = (const uint4*)g_hb;   // 16 uint4 per row

    float a[8];
#pragma unroll
    for (int j = 0; j < 8; j++) a[j] = 0.f;
    if (half == 0) {                          // self term once
        uint4 sv = __ldg(&hb4[node * 16 + hl]);
        acc8(sv, a);
    }

    for (int jb = 0; jb < deg; jb += 32) {
        int j = jb + lane;
        int myidx = (j < deg) ? g_csr[start + j] : 0;
        int cnt = min(32, deg - jb);
        int t = 0;
        for (; t + 8 <= cnt; t += 8) {        // 4 rows/lane, bf16x2 tree sum
            uint4 h[4];
#pragma unroll
            for (int u = 0; u < 4; u++) {
                int s = __shfl_sync(0xffffffffu, myidx, t + 2 * u + half);
                h[u] = __ldg(&hb4[s * 16 + hl]);
            }
            uint4 s01 = hadd2bf4(h[0], h[1]);
            uint4 s23 = hadd2bf4(h[2], h[3]);
            acc8(hadd2bf4(s01, s23), a);      // one fp32 flush per 4 rows
        }
        for (; t + 2 <= cnt; t += 2) {
            int s = __shfl_sync(0xffffffffu, myidx, t + half);
            uint4 hv = __ldg(&hb4[s * 16 + hl]);
            acc8(hv, a);
        }
        if (t < cnt) {                        // odd leftover: half 0 only
            int s = __shfl_sync(0xffffffffu, myidx, t);
            if (half == 0) {
                uint4 hv = __ldg(&hb4[s * 16 + hl]);
                acc8(hv, a);
            }
        }
    }
#pragma unroll
    for (int j = 0; j < 8; j++) a[j] += __shfl_xor_sync(0xffffffffu, a[j], 16);

    if (half == 0) {
        uint4 o;
        o.x = packbf(a[0] * dd, a[1] * dd);
        o.y = packbf(a[2] * dd, a[3] * dd);
        o.z = packbf(a[4] * dd, a[5] * dd);
        o.w = packbf(a[6] * dd, a[7] * dd);
        ((uint4*)g_gb)[node * 16 + hl] = o;
    }
}

// ---------------- K6: persistent bf16 tensor-core GEMM + epilogue -------------
__global__ void __launch_bounds__(256, 4) k_gemm(const float* __restrict__ W2,
                                                 const float* __restrict__ b2,
                                                 const float* __restrict__ Wc,
                                                 const void* batch) {
    extern __shared__ unsigned smu[];
    unsigned* w2t = smu;                 // [128][SB]
    unsigned* gsb = smu + HIDDEN * SB;   // [64][SB]

    int tid = threadIdx.x;
    int w = tid >> 5, lane = tid & 31;
    int is64 = g_is64;

    for (int i = tid; i < HIDDEN * HIDDEN / 8; i += 256) {
        int kp = i >> 5;
        int n4 = (i & 31) << 2;
        float4 a = __ldg((const float4*)&W2[(2 * kp) * HIDDEN + n4]);
        float4 b = __ldg((const float4*)&W2[(2 * kp + 1) * HIDDEN + n4]);
        w2t[(n4 + 0) * SB + kp] = packbf(a.x, b.x);
        w2t[(n4 + 1) * SB + kp] = packbf(a.y, b.y);
        w2t[(n4 + 2) * SB + kp] = packbf(a.z, b.z);
        w2t[(n4 + 3) * SB + kp] = packbf(a.w, b.w);
    }

    int rbase = (w >> 1) * 16;
    int nbase = (w & 1) * 64;
    int fr = lane >> 2;
    int fc = lane & 3;

    for (int tile = blockIdx.x; tile < NTILES; tile += gridDim.x) {
        __syncthreads();
        int base = tile * 64;
        for (int i = tid; i < 1024; i += 256) {
            int r = i >> 4, c4 = i & 15;
            int node = min(base + r, N_NODES - 1);
            uint4 v = __ldg((const uint4*)(g_gb + node * 32) + c4);
            *(uint4*)&gsb[r * SB + c4 * 4] = v;
        }
        __syncthreads();

        const unsigned* ga0 = &gsb[(rbase + fr) * SB];
        const unsigned* ga1 = &gsb[(rbase + fr + 8) * SB];
        float s_lo = 0.f, s_hi = 0.f;

#pragma unroll
        for (int nq = 0; nq < 2; nq++) {
            int nb = nbase + nq * 32;
            float4 acc[4];
#pragma unroll
            for (int n8 = 0; n8 < 4; n8++) {
                float2 bb = __ldg((const float2*)&b2[nb + n8 * 8 + 2 * fc]);
                acc[n8] = make_float4(bb.x, bb.y, bb.x, bb.y);
            }
#pragma unroll
            for (int k16 = 0; k16 < 8; k16++) {
                unsigned a0 = ga0[k16 * 8 + fc];
                unsigned a1 = ga1[k16 * 8 + fc];
                unsigned a2 = ga0[k16 * 8 + fc + 4];
                unsigned a3 = ga1[k16 * 8 + fc + 4];
#pragma unroll
                for (int n8 = 0; n8 < 4; n8++) {
                    const unsigned* wrow = &w2t[(nb + n8 * 8 + fr) * SB];
                    mma_bf16(acc[n8], a0, a1, a2, a3,
                             wrow[k16 * 8 + fc], wrow[k16 * 8 + fc + 4]);
                }
            }
#pragma unroll
            for (int n8 = 0; n8 < 4; n8++) {
                float2 wc = __ldg((const float2*)&Wc[nb + n8 * 8 + 2 * fc]);
                s_lo += fmaxf(acc[n8].x, 0.f) * wc.x + fmaxf(acc[n8].y, 0.f) * wc.y;
                s_hi += fmaxf(acc[n8].z, 0.f) * wc.x + fmaxf(acc[n8].w, 0.f) * wc.y;
            }
        }
#pragma unroll
        for (int off = 1; off <= 2; off <<= 1) {
            s_lo += __shfl_xor_sync(0xffffffffu, s_lo, off);
            s_hi += __shfl_xor_sync(0xffffffffu, s_hi, off);
        }
        if (fc == 0) {
            int node_lo = base + rbase + fr;
            int node_hi = node_lo + 8;
            if (node_lo < N_NODES) {
                int b = is64 ? (int)((const long long*)batch)[node_lo]
                             : ((const int*)batch)[node_lo];
                atomicAdd(&g_gsum[b], s_lo);
            }
            if (node_hi < N_NODES) {
                int b = is64 ? (int)((const long long*)batch)[node_hi]
                             : ((const int*)batch)[node_hi];
                atomicAdd(&g_gsum[b], s_hi);
            }
        }
    }
}

// ---------------- K7: counts via binary search on sorted batch + sigmoid ------
__global__ void k_out(float* __restrict__ out, const float* __restrict__ bc,
                      const void* batch) {
    int g = blockIdx.x * blockDim.x + threadIdx.x;
    if (g >= N_GRAPHS) return;
    int is64 = g_is64;
    int lo = 0, hi = N_NODES;
    while (lo < hi) {               // lower bound of g
        int m = (lo + hi) >> 1;
        int bv = is64 ? (int)((const long long*)batch)[m] : ((const int*)batch)[m];
        if (bv < g) lo = m + 1; else hi = m;
    }
    int lb = lo;
    lo = 0; hi = N_NODES;
    while (lo < hi) {               // upper bound of g
        int m = (lo + hi) >> 1;
        int bv = is64 ? (int)((const long long*)batch)[m] : ((const int*)batch)[m];
        if (bv <= g) lo = m + 1; else hi = m;
    }
    float cnt = fmaxf((float)(lo - lb), 1.0f);
    float logit = g_gsum[g] / cnt + bc[0];
    out[g] = 1.0f / (1.0f + expf(-logit));
}

// ---------------- launch --------------------------------------------------------
extern "C" void kernel_launch(void* const* d_in, const int* in_sizes, int n_in,
                              void* d_out, int out_size) {
    const float* x     = (const float*)d_in[0];
    const void*  ei    = d_in[1];
    const void*  batch = d_in[2];
    const float* W1    = (const float*)d_in[3];
    const float* b1    = (const float*)d_in[4];
    const float* W2    = (const float*)d_in[5];
    const float* b2    = (const float*)d_in[6];
    const float* Wc    = (const float*)d_in[7];
    const float* bc    = (const float*)d_in[8];
    float* out = (float*)d_out;

    const int SMEM = (HIDDEN + 64) * SB * 4;   // 52224 B
    static int smem_set = 0;
    if (!smem_set) {
        cudaFuncSetAttribute(k_gemm, cudaFuncAttributeMaxDynamicSharedMemorySize, SMEM);
        smem_set = 1;
    }

    k_init  <<<(N_NODES + 255) / 256, 256>>>((const unsigned*)ei, x);
    k_fill  <<<(N_EDGES + 255) / 256, 256>>>(ei);
    k_prep  <<<(N_NODES + 255) / 256, 256>>>();
    k_layer1<<<(N_NODES + 63) / 64, 256>>>(W1, b1);
    k_gather<<<(N_NODES + 7) / 8, 256>>>();
    k_gemm  <<<592, 256, SMEM>>>(W2, b2, Wc, batch);
    k_out   <<<(N_GRAPHS + 255) / 256, 256>>>(out, bc, batch);
}

// round 10
// speedup vs baseline: 1.0308x; 1.0308x over previous
#include <cuda_runtime.h>
#include <cuda_bf16.h>

#define N_NODES  100000
#define N_EDGES  1600000
#define N_GRAPHS 512
#define HIDDEN   128
#define CAP      96        // padded CSR; deg ~ Poisson(16), P(>=96) ~ 1e-45
#define SB       68        // smem row stride in uint32 (64 data + 4 pad)
#define NTILES   ((N_NODES + 63) / 64)
#define SENT     N_NODES   // sentinel node id -> zero rows

// ---------------- scratch (static device globals) ---------------------------
__device__ float4 g_x4 [N_NODES + 1];       // {x0, x1, x2, count->dinv}; +1 zero row
__device__ int    g_cnt[N_NODES];           // padded degree (multiple of 8)
__device__ int    g_csr[N_NODES * CAP];     // 38.4 MB padded CSR
__device__ uint2  g_hb [(N_NODES + 1) * 32];// h' rows bf16 (+ zero row)
__device__ uint2  g_gb [N_NODES * 32];      // G  rows bf16 (25.6 MB)
__device__ float  g_gsum[N_GRAPHS];
__device__ int    g_is64;

__device__ __forceinline__ float blo(unsigned w) { return __int_as_float(w << 16); }
__device__ __forceinline__ float bhi(unsigned w) { return __int_as_float(w & 0xffff0000u); }
__device__ __forceinline__ unsigned packbf(float lo, float hi) {
    __nv_bfloat162 p = __float22bfloat162_rn(make_float2(lo, hi));
    return *(const unsigned*)&p;
}
__device__ __forceinline__ void acc8(uint4 h, float* a) {
    a[0] += blo(h.x); a[1] += bhi(h.x);
    a[2] += blo(h.y); a[3] += bhi(h.y);
    a[4] += blo(h.z); a[5] += bhi(h.z);
    a[6] += blo(h.w); a[7] += bhi(h.w);
}
__device__ __forceinline__ void mma_bf16(float4& d, unsigned a0, unsigned a1,
                                         unsigned a2, unsigned a3,
                                         unsigned b0, unsigned b1) {
    asm("mma.sync.aligned.m16n8k16.row.col.f32.bf16.bf16.f32 "
        "{%0,%1,%2,%3}, {%4,%5,%6,%7}, {%8,%9}, {%0,%1,%2,%3};"
        : "+f"(d.x), "+f"(d.y), "+f"(d.z), "+f"(d.w)
        : "r"(a0), "r"(a1), "r"(a2), "r"(a3), "r"(b0), "r"(b1));
}

// ---------------- K1: init (x4 count=0, zero rows, gsum, dtype detect) --------
__global__ void k_init(const unsigned* __restrict__ ei, const float* __restrict__ x) {
    int i = blockIdx.x * blockDim.x + threadIdx.x;
    if (i == 0) {
        unsigned orv = 0;
#pragma unroll
        for (int t = 1; t < 32; t += 2) orv |= ei[t];   // int64 => high words zero
        g_is64 = (orv == 0u) ? 1 : 0;
        g_x4[SENT] = make_float4(0.f, 0.f, 0.f, 0.f);   // sentinel x row
    }
    if (i < 32) g_hb[(size_t)SENT * 32 + i] = make_uint2(0u, 0u);  // sentinel h' row
    if (i < N_NODES)
        g_x4[i] = make_float4(x[3 * i], x[3 * i + 1], x[3 * i + 2], 0.0f);
    if (i < N_GRAPHS) g_gsum[i] = 0.0f;
}

// ---------------- K2: build padded CSR; counter lives in g_x4[d].w ------------
__global__ void __launch_bounds__(256) k_fill(const void* ei) {
    int e = blockIdx.x * blockDim.x + threadIdx.x;
    if (e >= N_EDGES) return;
    int s, d;
    if (g_is64) {
        s = (int)((const long long*)ei)[e];
        d = (int)((const long long*)ei)[(long long)N_EDGES + e];
    } else {
        s = ((const int*)ei)[e];
        d = ((const int*)ei)[N_EDGES + e];
    }
    int slot = atomicAdd((int*)&g_x4[d].w, 1);
    if (slot < CAP) g_csr[d * CAP + slot] = s;
}

// ---------------- K3: count -> dinv; pad CSR rows to 8 with sentinel ----------
__global__ void k_prep() {
    int i = blockIdx.x * blockDim.x + threadIdx.x;
    if (i >= N_NODES) return;
    int c = min(__float_as_int(g_x4[i].w), CAP);
    int cp = min((c + 7) & ~7, CAP);            // pad to multiple of 8
    g_cnt[i] = cp;
    for (int j = c; j < cp; j++) g_csr[i * CAP + j] = SENT;
    g_x4[i].w = rsqrtf((float)(__float_as_int(g_x4[i].w) + 1));
}

// ---------------- K4: fused layer 1 (gather x*dinv + GEMV W1 -> bf16 h') ------
__global__ void __launch_bounds__(256) k_layer1(const float* __restrict__ W1,
                                                const float* __restrict__ b1) {
    int w = threadIdx.x >> 5, lane = threadIdx.x & 31;
    int g = lane >> 2, q = lane & 3;
    int nodeBase = blockIdx.x * 64 + w * 8;
    int nc = min(nodeBase + g, N_NODES - 1);
    float4 xs = g_x4[nc];
    float dd  = xs.w;
    int deg   = g_cnt[nc];
    int start = nc * CAP;

    float px = 0.f, py = 0.f, pz = 0.f;
    for (int j = q; j < deg; j += 4) {         // sentinel rows add 0
        int s = g_csr[start + j];
        float4 v = __ldg(&g_x4[s]);
        px = fmaf(v.x, v.w, px);
        py = fmaf(v.y, v.w, py);
        pz = fmaf(v.z, v.w, pz);
    }
#pragma unroll
    for (int off = 1; off <= 2; off <<= 1) {
        px += __shfl_xor_sync(0xffffffffu, px, off);
        py += __shfl_xor_sync(0xffffffffu, py, off);
        pz += __shfl_xor_sync(0xffffffffu, pz, off);
    }
    float v0 = dd * (px + xs.x * dd);
    float v1 = dd * (py + xs.y * dd);
    float v2 = dd * (pz + xs.z * dd);

    int c0 = lane << 2;
    const float4 w0 = *(const float4*)&W1[c0];
    const float4 w1 = *(const float4*)&W1[HIDDEN + c0];
    const float4 w2 = *(const float4*)&W1[2 * HIDDEN + c0];
    const float4 bb = *(const float4*)&b1[c0];

#pragma unroll
    for (int r = 0; r < 8; r++) {
        float u0 = __shfl_sync(0xffffffffu, v0, r * 4);
        float u1 = __shfl_sync(0xffffffffu, v1, r * 4);
        float u2 = __shfl_sync(0xffffffffu, v2, r * 4);
        float ud = __shfl_sync(0xffffffffu, dd, r * 4);
        int nd = nodeBase + r;
        if (nd >= N_NODES) break;
        float y0 = fmaf(u0, w0.x, fmaf(u1, w1.x, fmaf(u2, w2.x, bb.x)));
        float y1 = fmaf(u0, w0.y, fmaf(u1, w1.y, fmaf(u2, w2.y, bb.y)));
        float y2 = fmaf(u0, w0.z, fmaf(u1, w1.z, fmaf(u2, w2.z, bb.z)));
        float y3 = fmaf(u0, w0.w, fmaf(u1, w1.w, fmaf(u2, w2.w, bb.w)));
        y0 = fmaxf(y0, 0.f) * ud; y1 = fmaxf(y1, 0.f) * ud;
        y2 = fmaxf(y2, 0.f) * ud; y3 = fmaxf(y3, 0.f) * ud;
        uint2 o;
        o.x = packbf(y0, y1);
        o.y = packbf(y2, y3);
        g_hb[nd * 32 + lane] = o;
    }
}

// ---------------- K5: layer-2 gather — full 8-edge groups, no tails -----------
__global__ void __launch_bounds__(256) k_gather() {
    int w = threadIdx.x >> 5, lane = threadIdx.x & 31;
    int node = blockIdx.x * 8 + w;
    if (node >= N_NODES) return;
    int deg   = g_cnt[node];                  // multiple of 8
    float dd  = g_x4[node].w;
    int start = node * CAP;
    int half = lane >> 4;        // which edge of the pair this lane serves
    int hl   = lane & 15;        // uint4 slot within the 256-B row

    const uint4* hb4 = (const uint4*)g_hb;   // 16 uint4 per row

    float a[8];
#pragma unroll
    for (int j = 0; j < 8; j++) a[j] = 0.f;
    if (half == 0) {                          // self term once
        uint4 sv = __ldg(&hb4[node * 16 + hl]);
        acc8(sv, a);
    }

    for (int jb = 0; jb < deg; jb += 32) {
        int j = jb + lane;
        int myidx = (j < deg) ? g_csr[start + j] : SENT;
        int cnt = min(32, deg - jb);          // in {8,16,24,32}
        for (int t = 0; t < cnt; t += 8) {    // always full groups of 8
            uint4 h[4];
#pragma unroll
            for (int u = 0; u < 4; u++) {
                int s = __shfl_sync(0xffffffffu, myidx, t + 2 * u + half);
                h[u] = __ldg(&hb4[s * 16 + hl]);
            }
#pragma unroll
            for (int u = 0; u < 4; u++) acc8(h[u], a);
        }
    }
#pragma unroll
    for (int j = 0; j < 8; j++) a[j] += __shfl_xor_sync(0xffffffffu, a[j], 16);

    if (half == 0) {
        uint4 o;
        o.x = packbf(a[0] * dd, a[1] * dd);
        o.y = packbf(a[2] * dd, a[3] * dd);
        o.z = packbf(a[4] * dd, a[5] * dd);
        o.w = packbf(a[6] * dd, a[7] * dd);
        ((uint4*)g_gb)[node * 16 + hl] = o;
    }
}

// ---------------- K6: persistent bf16 tensor-core GEMM + epilogue -------------
__global__ void __launch_bounds__(256, 4) k_gemm(const float* __restrict__ W2,
                                                 const float* __restrict__ b2,
                                                 const float* __restrict__ Wc,
                                                 const void* batch) {
    extern __shared__ unsigned smu[];
    unsigned* w2t = smu;                 // [128][SB]
    unsigned* gsb = smu + HIDDEN * SB;   // [64][SB]

    int tid = threadIdx.x;
    int w = tid >> 5, lane = tid & 31;
    int is64 = g_is64;

    for (int i = tid; i < HIDDEN * HIDDEN / 8; i += 256) {
        int kp = i >> 5;
        int n4 = (i & 31) << 2;
        float4 a = __ldg((const float4*)&W2[(2 * kp) * HIDDEN + n4]);
        float4 b = __ldg((const float4*)&W2[(2 * kp + 1) * HIDDEN + n4]);
        w2t[(n4 + 0) * SB + kp] = packbf(a.x, b.x);
        w2t[(n4 + 1) * SB + kp] = packbf(a.y, b.y);
        w2t[(n4 + 2) * SB + kp] = packbf(a.z, b.z);
        w2t[(n4 + 3) * SB + kp] = packbf(a.w, b.w);
    }

    int rbase = (w >> 1) * 16;
    int nbase = (w & 1) * 64;
    int fr = lane >> 2;
    int fc = lane & 3;

    for (int tile = blockIdx.x; tile < NTILES; tile += gridDim.x) {
        __syncthreads();
        int base = tile * 64;
        for (int i = tid; i < 1024; i += 256) {
            int r = i >> 4, c4 = i & 15;
            int node = min(base + r, N_NODES - 1);
            uint4 v = __ldg((const uint4*)(g_gb + node * 32) + c4);
            *(uint4*)&gsb[r * SB + c4 * 4] = v;
        }
        __syncthreads();

        const unsigned* ga0 = &gsb[(rbase + fr) * SB];
        const unsigned* ga1 = &gsb[(rbase + fr + 8) * SB];
        float s_lo = 0.f, s_hi = 0.f;

#pragma unroll
        for (int nq = 0; nq < 2; nq++) {
            int nb = nbase + nq * 32;
            float4 acc[4];
#pragma unroll
            for (int n8 = 0; n8 < 4; n8++) {
                float2 bb = __ldg((const float2*)&b2[nb + n8 * 8 + 2 * fc]);
                acc[n8] = make_float4(bb.x, bb.y, bb.x, bb.y);
            }
#pragma unroll
            for (int k16 = 0; k16 < 8; k16++) {
                unsigned a0 = ga0[k16 * 8 + fc];
                unsigned a1 = ga1[k16 * 8 + fc];
                unsigned a2 = ga0[k16 * 8 + fc + 4];
                unsigned a3 = ga1[k16 * 8 + fc + 4];
#pragma unroll
                for (int n8 = 0; n8 < 4; n8++) {
                    const unsigned* wrow = &w2t[(nb + n8 * 8 + fr) * SB];
                    mma_bf16(acc[n8], a0, a1, a2, a3,
                             wrow[k16 * 8 + fc], wrow[k16 * 8 + fc + 4]);
                }
            }
#pragma unroll
            for (int n8 = 0; n8 < 4; n8++) {
                float2 wc = __ldg((const float2*)&Wc[nb + n8 * 8 + 2 * fc]);
                s_lo += fmaxf(acc[n8].x, 0.f) * wc.x + fmaxf(acc[n8].y, 0.f) * wc.y;
                s_hi += fmaxf(acc[n8].z, 0.f) * wc.x + fmaxf(acc[n8].w, 0.f) * wc.y;
            }
        }
#pragma unroll
        for (int off = 1; off <= 2; off <<= 1) {
            s_lo += __shfl_xor_sync(0xffffffffu, s_lo, off);
            s_hi += __shfl_xor_sync(0xffffffffu, s_hi, off);
        }
        if (fc == 0) {
            int node_lo = base + rbase + fr;
            int node_hi = node_lo + 8;
            if (node_lo < N_NODES) {
                int b = is64 ? (int)((const long long*)batch)[node_lo]
                             : ((const int*)batch)[node_lo];
                atomicAdd(&g_gsum[b], s_lo);
            }
            if (node_hi < N_NODES) {
                int b = is64 ? (int)((const long long*)batch)[node_hi]
                             : ((const int*)batch)[node_hi];
                atomicAdd(&g_gsum[b], s_hi);
            }
        }
    }
}

// ---------------- K7: counts via binary search on sorted batch + sigmoid ------
__global__ void k_out(float* __restrict__ out, const float* __restrict__ bc,
                      const void* batch) {
    int g = blockIdx.x * blockDim.x + threadIdx.x;
    if (g >= N_GRAPHS) return;
    int is64 = g_is64;
    int lo = 0, hi = N_NODES;
    while (lo < hi) {               // lower bound of g
        int m = (lo + hi) >> 1;
        int bv = is64 ? (int)((const long long*)batch)[m] : ((const int*)batch)[m];
        if (bv < g) lo = m + 1; else hi = m;
    }
    int lb = lo;
    lo = 0; hi = N_NODES;
    while (lo < hi) {               // upper bound of g
        int m = (lo + hi) >> 1;
        int bv = is64 ? (int)((const long long*)batch)[m] : ((const int*)batch)[m];
        if (bv <= g) lo = m + 1; else hi = m;
    }
    float cnt = fmaxf((float)(lo - lb), 1.0f);
    float logit = g_gsum[g] / cnt + bc[0];
    out[g] = 1.0f / (1.0f + expf(-logit));
}

// ---------------- launch --------------------------------------------------------
extern "C" void kernel_launch(void* const* d_in, const int* in_sizes, int n_in,
                              void* d_out, int out_size) {
    const float* x     = (const float*)d_in[0];
    const void*  ei    = d_in[1];
    const void*  batch = d_in[2];
    const float* W1    = (const float*)d_in[3];
    const float* b1    = (const float*)d_in[4];
    const float* W2    = (const float*)d_in[5];
    const float* b2    = (const float*)d_in[6];
    const float* Wc    = (const float*)d_in[7];
    const float* bc    = (const float*)d_in[8];
    float* out = (float*)d_out;

    const int SMEM = (HIDDEN + 64) * SB * 4;   // 52224 B
    static int smem_set = 0;
    if (!smem_set) {
        cudaFuncSetAttribute(k_gemm, cudaFuncAttributeMaxDynamicSharedMemorySize, SMEM);
        smem_set = 1;
    }

    k_init  <<<(N_NODES + 255) / 256, 256>>>((const unsigned*)ei, x);
    k_fill  <<<(N_EDGES + 255) / 256, 256>>>(ei);
    k_prep  <<<(N_NODES + 255) / 256, 256>>>();
    k_layer1<<<(N_NODES + 63) / 64, 256>>>(W1, b1);
    k_gather<<<(N_NODES + 7) / 8, 256>>>();
    k_gemm  <<<592, 256, SMEM>>>(W2, b2, Wc, batch);
    k_out   <<<(N_GRAPHS + 255) / 256, 256>>>(out, bc, batch);
}

// round 11
// speedup vs baseline: 1.0512x; 1.0197x over previous
#include <cuda_runtime.h>
#include <cuda_bf16.h>

#define N_NODES  100000
#define N_EDGES  1600000
#define N_GRAPHS 512
#define HIDDEN   128
#define CAP      96        // padded CSR; deg ~ Poisson(16), P(>=96) ~ 1e-45
#define SB       68        // smem row stride in uint32 (64 data + 4 pad)
#define NTILES   ((N_NODES + 63) / 64)

// ---------------- scratch (static device globals) ---------------------------
__device__ float4 g_x4 [N_NODES];           // {x0, x1, x2, (int)count_bits}
__device__ int    g_csr[N_NODES * CAP];     // 38.4 MB padded CSR
__device__ uint2  g_hb [N_NODES * 32];      // h' rows bf16 (25.6 MB)
__device__ uint2  g_gb [N_NODES * 32];      // G  rows bf16 (25.6 MB)
__device__ float  g_gsum[N_GRAPHS];
__device__ int    g_is64;

__device__ __forceinline__ float blo(unsigned w) { return __int_as_float(w << 16); }
__device__ __forceinline__ float bhi(unsigned w) { return __int_as_float(w & 0xffff0000u); }
__device__ __forceinline__ unsigned packbf(float lo, float hi) {
    __nv_bfloat162 p = __float22bfloat162_rn(make_float2(lo, hi));
    return *(const unsigned*)&p;
}
__device__ __forceinline__ unsigned hadd2bf(unsigned a, unsigned b) {
    __nv_bfloat162 r = __hadd2(*(const __nv_bfloat162*)&a, *(const __nv_bfloat162*)&b);
    return *(const unsigned*)&r;
}
__device__ __forceinline__ uint4 hadd2bf4(uint4 a, uint4 b) {
    uint4 r;
    r.x = hadd2bf(a.x, b.x); r.y = hadd2bf(a.y, b.y);
    r.z = hadd2bf(a.z, b.z); r.w = hadd2bf(a.w, b.w);
    return r;
}
__device__ __forceinline__ void acc8(uint4 h, float* a) {
    a[0] += blo(h.x); a[1] += bhi(h.x);
    a[2] += blo(h.y); a[3] += bhi(h.y);
    a[4] += blo(h.z); a[5] += bhi(h.z);
    a[6] += blo(h.w); a[7] += bhi(h.w);
}
__device__ __forceinline__ void mma_bf16(float4& d, unsigned a0, unsigned a1,
                                         unsigned a2, unsigned a3,
                                         unsigned b0, unsigned b1) {
    asm("mma.sync.aligned.m16n8k16.row.col.f32.bf16.bf16.f32 "
        "{%0,%1,%2,%3}, {%4,%5,%6,%7}, {%8,%9}, {%0,%1,%2,%3};"
        : "+f"(d.x), "+f"(d.y), "+f"(d.z), "+f"(d.w)
        : "r"(a0), "r"(a1), "r"(a2), "r"(a3), "r"(b0), "r"(b1));
}

// ---------------- K1: init (x4 count=0, gsum, dtype detect) -------------------
__global__ void k_init(const unsigned* __restrict__ ei, const float* __restrict__ x) {
    int i = blockIdx.x * blockDim.x + threadIdx.x;
    if (i == 0) {
        unsigned orv = 0;
#pragma unroll
        for (int t = 1; t < 32; t += 2) orv |= ei[t];   // int64 => high words zero
        g_is64 = (orv == 0u) ? 1 : 0;
    }
    if (i < N_NODES)
        g_x4[i] = make_float4(x[3 * i], x[3 * i + 1], x[3 * i + 2], 0.0f);
    if (i < N_GRAPHS) g_gsum[i] = 0.0f;
}

// ---------------- K2: build padded CSR; counter lives in g_x4[d].w ------------
__global__ void __launch_bounds__(256) k_fill(const void* ei) {
    int e = blockIdx.x * blockDim.x + threadIdx.x;
    if (e >= N_EDGES) return;
    int s, d;
    if (g_is64) {
        s = (int)((const long long*)ei)[e];
        d = (int)((const long long*)ei)[(long long)N_EDGES + e];
    } else {
        s = ((const int*)ei)[e];
        d = ((const int*)ei)[N_EDGES + e];
    }
    int slot = atomicAdd((int*)&g_x4[d].w, 1);
    if (slot < CAP) g_csr[d * CAP + slot] = s;
}

// ---------------- K3: fused layer 1 (inline neighbor dinv) --------------------
__global__ void __launch_bounds__(256) k_layer1(const float* __restrict__ W1,
                                                const float* __restrict__ b1) {
    int w = threadIdx.x >> 5, lane = threadIdx.x & 31;
    int g = lane >> 2, q = lane & 3;
    int nodeBase = blockIdx.x * 64 + w * 8;
    int nc = min(nodeBase + g, N_NODES - 1);
    float4 xs = g_x4[nc];
    int cr    = __float_as_int(xs.w);
    int deg   = min(cr, CAP);
    float dd  = rsqrtf((float)(cr + 1));
    int start = nc * CAP;

    float px = 0.f, py = 0.f, pz = 0.f;
    for (int j = q; j < deg; j += 4) {
        int s = g_csr[start + j];
        float4 v = __ldg(&g_x4[s]);
        float ds = rsqrtf((float)(__float_as_int(v.w) + 1));
        px = fmaf(v.x, ds, px);
        py = fmaf(v.y, ds, py);
        pz = fmaf(v.z, ds, pz);
    }
#pragma unroll
    for (int off = 1; off <= 2; off <<= 1) {
        px += __shfl_xor_sync(0xffffffffu, px, off);
        py += __shfl_xor_sync(0xffffffffu, py, off);
        pz += __shfl_xor_sync(0xffffffffu, pz, off);
    }
    float v0 = dd * (px + xs.x * dd);
    float v1 = dd * (py + xs.y * dd);
    float v2 = dd * (pz + xs.z * dd);

    int c0 = lane << 2;
    const float4 w0 = *(const float4*)&W1[c0];
    const float4 w1 = *(const float4*)&W1[HIDDEN + c0];
    const float4 w2 = *(const float4*)&W1[2 * HIDDEN + c0];
    const float4 bb = *(const float4*)&b1[c0];

#pragma unroll
    for (int r = 0; r < 8; r++) {
        float u0 = __shfl_sync(0xffffffffu, v0, r * 4);
        float u1 = __shfl_sync(0xffffffffu, v1, r * 4);
        float u2 = __shfl_sync(0xffffffffu, v2, r * 4);
        float ud = __shfl_sync(0xffffffffu, dd, r * 4);
        int nd = nodeBase + r;
        if (nd >= N_NODES) break;
        float y0 = fmaf(u0, w0.x, fmaf(u1, w1.x, fmaf(u2, w2.x, bb.x)));
        float y1 = fmaf(u0, w0.y, fmaf(u1, w1.y, fmaf(u2, w2.y, bb.y)));
        float y2 = fmaf(u0, w0.z, fmaf(u1, w1.z, fmaf(u2, w2.z, bb.z)));
        float y3 = fmaf(u0, w0.w, fmaf(u1, w1.w, fmaf(u2, w2.w, bb.w)));
        y0 = fmaxf(y0, 0.f) * ud; y1 = fmaxf(y1, 0.f) * ud;
        y2 = fmaxf(y2, 0.f) * ud; y3 = fmaxf(y3, 0.f) * ud;
        uint2 o;
        o.x = packbf(y0, y1);
        o.y = packbf(y2, y3);
        g_hb[nd * 32 + lane] = o;
    }
}

// ---------------- K4: layer-2 gather — depth-1 bf16x2 pairing ------------------
__global__ void __launch_bounds__(256) k_gather() {
    int w = threadIdx.x >> 5, lane = threadIdx.x & 31;
    int node = blockIdx.x * 8 + w;
    if (node >= N_NODES) return;
    int cr    = __float_as_int(g_x4[node].w);
    int deg   = min(cr, CAP);
    float dd  = rsqrtf((float)(cr + 1));
    int start = node * CAP;
    int half = lane >> 4;        // which edge of the pair this lane serves
    int hl   = lane & 15;        // uint4 slot within the 256-B row

    const uint4* hb4 = (const uint4*)g_hb;   // 16 uint4 per row

    float a[8];
#pragma unroll
    for (int j = 0; j < 8; j++) a[j] = 0.f;
    if (half == 0) {                          // self term once
        uint4 sv = __ldg(&hb4[node * 16 + hl]);
        acc8(sv, a);
    }

    for (int jb = 0; jb < deg; jb += 32) {
        int j = jb + lane;
        int myidx = (j < deg) ? g_csr[start + j] : 0;
        int cnt = min(32, deg - jb);
        int t = 0;
        for (; t + 8 <= cnt; t += 8) {        // 4 rows/lane in flight
            uint4 h[4];
#pragma unroll
            for (int u = 0; u < 4; u++) {
                int s = __shfl_sync(0xffffffffu, myidx, t + 2 * u + half);
                h[u] = __ldg(&hb4[s * 16 + hl]);
            }
            // depth-1 pairing: independent HADD2 pairs, two parallel flushes
            uint4 p01 = hadd2bf4(h[0], h[1]);
            uint4 p23 = hadd2bf4(h[2], h[3]);
            acc8(p01, a);
            acc8(p23, a);
        }
        for (; t + 2 <= cnt; t += 2) {
            int s = __shfl_sync(0xffffffffu, myidx, t + half);
            uint4 hv = __ldg(&hb4[s * 16 + hl]);
            acc8(hv, a);
        }
        if (t < cnt) {                        // odd leftover: half 0 only
            int s = __shfl_sync(0xffffffffu, myidx, t);
            if (half == 0) {
                uint4 hv = __ldg(&hb4[s * 16 + hl]);
                acc8(hv, a);
            }
        }
    }
#pragma unroll
    for (int j = 0; j < 8; j++) a[j] += __shfl_xor_sync(0xffffffffu, a[j], 16);

    if (half == 0) {
        uint4 o;
        o.x = packbf(a[0] * dd, a[1] * dd);
        o.y = packbf(a[2] * dd, a[3] * dd);
        o.z = packbf(a[4] * dd, a[5] * dd);
        o.w = packbf(a[6] * dd, a[7] * dd);
        ((uint4*)g_gb)[node * 16 + hl] = o;
    }
}

// ---------------- K5: persistent bf16 tensor-core GEMM + epilogue -------------
__global__ void __launch_bounds__(256, 4) k_gemm(const float* __restrict__ W2,
                                                 const float* __restrict__ b2,
                                                 const float* __restrict__ Wc,
                                                 const void* batch) {
    extern __shared__ unsigned smu[];
    unsigned* w2t = smu;                 // [128][SB]
    unsigned* gsb = smu + HIDDEN * SB;   // [64][SB]

    int tid = threadIdx.x;
    int w = tid >> 5, lane = tid & 31;
    int is64 = g_is64;

    for (int i = tid; i < HIDDEN * HIDDEN / 8; i += 256) {
        int kp = i >> 5;
        int n4 = (i & 31) << 2;
        float4 a = __ldg((const float4*)&W2[(2 * kp) * HIDDEN + n4]);
        float4 b = __ldg((const float4*)&W2[(2 * kp + 1) * HIDDEN + n4]);
        w2t[(n4 + 0) * SB + kp] = packbf(a.x, b.x);
        w2t[(n4 + 1) * SB + kp] = packbf(a.y, b.y);
        w2t[(n4 + 2) * SB + kp] = packbf(a.z, b.z);
        w2t[(n4 + 3) * SB + kp] = packbf(a.w, b.w);
    }

    int rbase = (w >> 1) * 16;
    int nbase = (w & 1) * 64;
    int fr = lane >> 2;
    int fc = lane & 3;

    for (int tile = blockIdx.x; tile < NTILES; tile += gridDim.x) {
        __syncthreads();
        int base = tile * 64;
        for (int i = tid; i < 1024; i += 256) {
            int r = i >> 4, c4 = i & 15;
            int node = min(base + r, N_NODES - 1);
            uint4 v = __ldg((const uint4*)(g_gb + node * 32) + c4);
            *(uint4*)&gsb[r * SB + c4 * 4] = v;
        }
        __syncthreads();

        const unsigned* ga0 = &gsb[(rbase + fr) * SB];
        const unsigned* ga1 = &gsb[(rbase + fr + 8) * SB];
        float s_lo = 0.f, s_hi = 0.f;

#pragma unroll
        for (int nq = 0; nq < 2; nq++) {
            int nb = nbase + nq * 32;
            float4 acc[4];
#pragma unroll
            for (int n8 = 0; n8 < 4; n8++) {
                float2 bb = __ldg((const float2*)&b2[nb + n8 * 8 + 2 * fc]);
                acc[n8] = make_float4(bb.x, bb.y, bb.x, bb.y);
            }
#pragma unroll
            for (int k16 = 0; k16 < 8; k16++) {
                unsigned a0 = ga0[k16 * 8 + fc];
                unsigned a1 = ga1[k16 * 8 + fc];
                unsigned a2 = ga0[k16 * 8 + fc + 4];
                unsigned a3 = ga1[k16 * 8 + fc + 4];
#pragma unroll
                for (int n8 = 0; n8 < 4; n8++) {
                    const unsigned* wrow = &w2t[(nb + n8 * 8 + fr) * SB];
                    mma_bf16(acc[n8], a0, a1, a2, a3,
                             wrow[k16 * 8 + fc], wrow[k16 * 8 + fc + 4]);
                }
            }
#pragma unroll
            for (int n8 = 0; n8 < 4; n8++) {
                float2 wc = __ldg((const float2*)&Wc[nb + n8 * 8 + 2 * fc]);
                s_lo += fmaxf(acc[n8].x, 0.f) * wc.x + fmaxf(acc[n8].y, 0.f) * wc.y;
                s_hi += fmaxf(acc[n8].z, 0.f) * wc.x + fmaxf(acc[n8].w, 0.f) * wc.y;
            }
        }
#pragma unroll
        for (int off = 1; off <= 2; off <<= 1) {
            s_lo += __shfl_xor_sync(0xffffffffu, s_lo, off);
            s_hi += __shfl_xor_sync(0xffffffffu, s_hi, off);
        }
        if (fc == 0) {
            int node_lo = base + rbase + fr;
            int node_hi = node_lo + 8;
            if (node_lo < N_NODES) {
                int b = is64 ? (int)((const long long*)batch)[node_lo]
                             : ((const int*)batch)[node_lo];
                atomicAdd(&g_gsum[b], s_lo);
            }
            if (node_hi < N_NODES) {
                int b = is64 ? (int)((const long long*)batch)[node_hi]
                             : ((const int*)batch)[node_hi];
                atomicAdd(&g_gsum[b], s_hi);
            }
        }
    }
}

// ---------------- K6: counts via binary search on sorted batch + sigmoid ------
__global__ void k_out(float* __restrict__ out, const float* __restrict__ bc,
                      const void* batch) {
    int g = blockIdx.x * blockDim.x + threadIdx.x;
    if (g >= N_GRAPHS) return;
    int is64 = g_is64;
    int lo = 0, hi = N_NODES;
    while (lo < hi) {               // lower bound of g
        int m = (lo + hi) >> 1;
        int bv = is64 ? (int)((const long long*)batch)[m] : ((const int*)batch)[m];
        if (bv < g) lo = m + 1; else hi = m;
    }
    int lb = lo;
    lo = 0; hi = N_NODES;
    while (lo < hi) {               // upper bound of g
        int m = (lo + hi) >> 1;
        int bv = is64 ? (int)((const long long*)batch)[m] : ((const int*)batch)[m];
        if (bv <= g) lo = m + 1; else hi = m;
    }
    float cnt = fmaxf((float)(lo - lb), 1.0f);
    float logit = g_gsum[g] / cnt + bc[0];
    out[g] = 1.0f / (1.0f + expf(-logit));
}

// ---------------- launch --------------------------------------------------------
extern "C" void kernel_launch(void* const* d_in, const int* in_sizes, int n_in,
                              void* d_out, int out_size) {
    const float* x     = (const float*)d_in[0];
    const void*  ei    = d_in[1];
    const void*  batch = d_in[2];
    const float* W1    = (const float*)d_in[3];
    const float* b1    = (const float*)d_in[4];
    const float* W2    = (const float*)d_in[5];
    const float* b2    = (const float*)d_in[6];
    const float* Wc    = (const float*)d_in[7];
    const float* bc    = (const float*)d_in[8];
    float* out = (float*)d_out;

    const int SMEM = (HIDDEN + 64) * SB * 4;   // 52224 B
    static int smem_set = 0;
    if (!smem_set) {
        cudaFuncSetAttribute(k_gemm, cudaFuncAttributeMaxDynamicSharedMemorySize, SMEM);
        smem_set = 1;
    }

    k_init  <<<(N_NODES + 255) / 256, 256>>>((const unsigned*)ei, x);
    k_fill  <<<(N_EDGES + 255) / 256, 256>>>(ei);
    k_layer1<<<(N_NODES + 63) / 64, 256>>>(W1, b1);
    k_gather<<<(N_NODES + 7) / 8, 256>>>();          // <- profiled slot (#4)
    k_gemm  <<<592, 256, SMEM>>>(W2, b2, Wc, batch);
    k_out   <<<(N_GRAPHS + 255) / 256, 256>>>(out, bc, batch);
}

// round 12
// speedup vs baseline: 1.1657x; 1.1090x over previous
#include <cuda_runtime.h>
#include <cuda_bf16.h>

#define N_NODES  100000
#define N_EDGES  1600000
#define N_GRAPHS 512
#define HIDDEN   128
#define CAP      96        // padded CSR; deg ~ Poisson(16), P(>=96) ~ 1e-45
#define SB       68        // smem row stride in uint32 (64 data + 4 pad)
#define NTILES   ((N_NODES + 63) / 64)

// ---------------- scratch (static device globals) ---------------------------
__device__ float4   g_x4 [N_NODES];          // {x0, x1, x2, (int)count_bits}
__device__ int      g_csr[N_NODES * CAP];    // 38.4 MB padded CSR
__device__ unsigned g_h8 [N_NODES * 32];     // h' rows e4m3, 128 B/row (12.8 MB)
__device__ uint2    g_gb [N_NODES * 32];     // G  rows bf16 (25.6 MB)
__device__ float    g_gsum[N_GRAPHS];
__device__ int      g_is64;

// ---------------- helpers ----------------------------------------------------
__device__ __forceinline__ unsigned packbf(float lo, float hi) {
    __nv_bfloat162 p = __float22bfloat162_rn(make_float2(lo, hi));
    return *(const unsigned*)&p;
}
// 4 fp32 -> 4 e4m3 packed in a u32 (y0 in lowest byte)
__device__ __forceinline__ unsigned pack_e4m3_4(float y0, float y1, float y2, float y3) {
    unsigned short lo, hi;
    asm("cvt.rn.satfinite.e4m3x2.f32 %0, %1, %2;" : "=h"(lo) : "f"(y1), "f"(y0));
    asm("cvt.rn.satfinite.e4m3x2.f32 %0, %1, %2;" : "=h"(hi) : "f"(y3), "f"(y2));
    unsigned r;
    asm("mov.b32 %0, {%1,%2};" : "=r"(r) : "h"(lo), "h"(hi));
    return r;
}
// u32 of 4 e4m3 -> two f16x2 (exact widening)
__device__ __forceinline__ void fp8quad_to_h2(unsigned w, unsigned& f01, unsigned& f23) {
    unsigned short l, h;
    asm("mov.b32 {%0,%1}, %2;" : "=h"(l), "=h"(h) : "r"(w));
    asm("cvt.rn.f16x2.e4m3x2 %0, %1;" : "=r"(f01) : "h"(l));
    asm("cvt.rn.f16x2.e4m3x2 %0, %1;" : "=r"(f23) : "h"(h));
}
__device__ __forceinline__ unsigned hadd2f16(unsigned a, unsigned b) {
    unsigned r; asm("add.rn.f16x2 %0, %1, %2;" : "=r"(r) : "r"(a), "r"(b)); return r;
}
__device__ __forceinline__ void h2_to_f32(unsigned p, float& lo, float& hi) {
    unsigned short l, h;
    asm("mov.b32 {%0,%1}, %2;" : "=h"(l), "=h"(h) : "r"(p));
    asm("cvt.f32.f16 %0, %1;" : "=f"(lo) : "h"(l));
    asm("cvt.f32.f16 %0, %1;" : "=f"(hi) : "h"(h));
}
__device__ __forceinline__ void mma_bf16(float4& d, unsigned a0, unsigned a1,
                                         unsigned a2, unsigned a3,
                                         unsigned b0, unsigned b1) {
    asm("mma.sync.aligned.m16n8k16.row.col.f32.bf16.bf16.f32 "
        "{%0,%1,%2,%3}, {%4,%5,%6,%7}, {%8,%9}, {%0,%1,%2,%3};"
        : "+f"(d.x), "+f"(d.y), "+f"(d.z), "+f"(d.w)
        : "r"(a0), "r"(a1), "r"(a2), "r"(a3), "r"(b0), "r"(b1));
}

// ---------------- K1: init (x4 count=0, gsum, dtype detect) -------------------
__global__ void k_init(const unsigned* __restrict__ ei, const float* __restrict__ x) {
    int i = blockIdx.x * blockDim.x + threadIdx.x;
    if (i == 0) {
        unsigned orv = 0;
#pragma unroll
        for (int t = 1; t < 32; t += 2) orv |= ei[t];   // int64 => high words zero
        g_is64 = (orv == 0u) ? 1 : 0;
    }
    if (i < N_NODES)
        g_x4[i] = make_float4(x[3 * i], x[3 * i + 1], x[3 * i + 2], 0.0f);
    if (i < N_GRAPHS) g_gsum[i] = 0.0f;
}

// ---------------- K2: build padded CSR; counter lives in g_x4[d].w ------------
__global__ void __launch_bounds__(256) k_fill(const void* ei) {
    int e = blockIdx.x * blockDim.x + threadIdx.x;
    if (e >= N_EDGES) return;
    int s, d;
    if (g_is64) {
        s = (int)((const long long*)ei)[e];
        d = (int)((const long long*)ei)[(long long)N_EDGES + e];
    } else {
        s = ((const int*)ei)[e];
        d = ((const int*)ei)[N_EDGES + e];
    }
    int slot = atomicAdd((int*)&g_x4[d].w, 1);
    if (slot < CAP) g_csr[d * CAP + slot] = s;
}

// ---------------- K3: fused layer 1 (inline neighbor dinv -> fp8 h') ----------
__global__ void __launch_bounds__(256) k_layer1(const float* __restrict__ W1,
                                                const float* __restrict__ b1) {
    int w = threadIdx.x >> 5, lane = threadIdx.x & 31;
    int g = lane >> 2, q = lane & 3;
    int nodeBase = blockIdx.x * 64 + w * 8;
    int nc = min(nodeBase + g, N_NODES - 1);
    float4 xs = g_x4[nc];
    int cr    = __float_as_int(xs.w);
    int deg   = min(cr, CAP);
    float dd  = rsqrtf((float)(cr + 1));
    int start = nc * CAP;

    float px = 0.f, py = 0.f, pz = 0.f;
    for (int j = q; j < deg; j += 4) {
        int s = g_csr[start + j];
        float4 v = __ldg(&g_x4[s]);
        float ds = rsqrtf((float)(__float_as_int(v.w) + 1));
        px = fmaf(v.x, ds, px);
        py = fmaf(v.y, ds, py);
        pz = fmaf(v.z, ds, pz);
    }
#pragma unroll
    for (int off = 1; off <= 2; off <<= 1) {
        px += __shfl_xor_sync(0xffffffffu, px, off);
        py += __shfl_xor_sync(0xffffffffu, py, off);
        pz += __shfl_xor_sync(0xffffffffu, pz, off);
    }
    float v0 = dd * (px + xs.x * dd);
    float v1 = dd * (py + xs.y * dd);
    float v2 = dd * (pz + xs.z * dd);

    int c0 = lane << 2;
    const float4 w0 = *(const float4*)&W1[c0];
    const float4 w1 = *(const float4*)&W1[HIDDEN + c0];
    const float4 w2 = *(const float4*)&W1[2 * HIDDEN + c0];
    const float4 bb = *(const float4*)&b1[c0];

#pragma unroll
    for (int r = 0; r < 8; r++) {
        float u0 = __shfl_sync(0xffffffffu, v0, r * 4);
        float u1 = __shfl_sync(0xffffffffu, v1, r * 4);
        float u2 = __shfl_sync(0xffffffffu, v2, r * 4);
        float ud = __shfl_sync(0xffffffffu, dd, r * 4);
        int nd = nodeBase + r;
        if (nd >= N_NODES) break;
        float y0 = fmaf(u0, w0.x, fmaf(u1, w1.x, fmaf(u2, w2.x, bb.x)));
        float y1 = fmaf(u0, w0.y, fmaf(u1, w1.y, fmaf(u2, w2.y, bb.y)));
        float y2 = fmaf(u0, w0.z, fmaf(u1, w1.z, fmaf(u2, w2.z, bb.z)));
        float y3 = fmaf(u0, w0.w, fmaf(u1, w1.w, fmaf(u2, w2.w, bb.w)));
        y0 = fmaxf(y0, 0.f) * ud; y1 = fmaxf(y1, 0.f) * ud;
        y2 = fmaxf(y2, 0.f) * ud; y3 = fmaxf(y3, 0.f) * ud;
        g_h8[nd * 32 + lane] = pack_e4m3_4(y0, y1, y2, y3);   // 128B coalesced row
    }
}

// ---------------- K4: layer-2 gather — fp8 rows, f16x2 accumulation -----------
// 2 edges/warp: 16 lanes per row, uint2 (8B = 8 fp8 cols) per lane.
__global__ void __launch_bounds__(256) k_gather() {
    int w = threadIdx.x >> 5, lane = threadIdx.x & 31;
    int node = blockIdx.x * 8 + w;
    if (node >= N_NODES) return;
    int cr    = __float_as_int(g_x4[node].w);
    int deg   = min(cr, CAP);
    float dd  = rsqrtf((float)(cr + 1));
    int start = node * CAP;
    int half = lane >> 4;
    int hl   = lane & 15;

    const uint2* h8 = (const uint2*)g_h8;    // 16 uint2 per 128B row

    unsigned hacc0 = 0u, hacc1 = 0u, hacc2 = 0u, hacc3 = 0u;   // f16x2 accums
    if (half == 0) {                          // self term once
        uint2 sv = __ldg(&h8[node * 16 + hl]);
        fp8quad_to_h2(sv.x, hacc0, hacc1);
        fp8quad_to_h2(sv.y, hacc2, hacc3);
    }

    for (int jb = 0; jb < deg; jb += 32) {
        int j = jb + lane;
        int myidx = (j < deg) ? g_csr[start + j] : 0;
        int cnt = min(32, deg - jb);
        int t = 0;
        for (; t + 8 <= cnt; t += 8) {        // 4 row-loads in flight per lane
            uint2 h[4];
#pragma unroll
            for (int u = 0; u < 4; u++) {
                int s = __shfl_sync(0xffffffffu, myidx, t + 2 * u + half);
                h[u] = __ldg(&h8[s * 16 + hl]);
            }
            unsigned a01, a23, a45, a67, b01, b23, b45, b67;
            fp8quad_to_h2(h[0].x, a01, a23); fp8quad_to_h2(h[0].y, a45, a67);
            fp8quad_to_h2(h[1].x, b01, b23); fp8quad_to_h2(h[1].y, b45, b67);
            hacc0 = hadd2f16(hacc0, hadd2f16(a01, b01));
            hacc1 = hadd2f16(hacc1, hadd2f16(a23, b23));
            hacc2 = hadd2f16(hacc2, hadd2f16(a45, b45));
            hacc3 = hadd2f16(hacc3, hadd2f16(a67, b67));
            fp8quad_to_h2(h[2].x, a01, a23); fp8quad_to_h2(h[2].y, a45, a67);
            fp8quad_to_h2(h[3].x, b01, b23); fp8quad_to_h2(h[3].y, b45, b67);
            hacc0 = hadd2f16(hacc0, hadd2f16(a01, b01));
            hacc1 = hadd2f16(hacc1, hadd2f16(a23, b23));
            hacc2 = hadd2f16(hacc2, hadd2f16(a45, b45));
            hacc3 = hadd2f16(hacc3, hadd2f16(a67, b67));
        }
        for (; t + 2 <= cnt; t += 2) {
            int s = __shfl_sync(0xffffffffu, myidx, t + half);
            uint2 hv = __ldg(&h8[s * 16 + hl]);
            unsigned f01, f23, f45, f67;
            fp8quad_to_h2(hv.x, f01, f23);
            fp8quad_to_h2(hv.y, f45, f67);
            hacc0 = hadd2f16(hacc0, f01);
            hacc1 = hadd2f16(hacc1, f23);
            hacc2 = hadd2f16(hacc2, f45);
            hacc3 = hadd2f16(hacc3, f67);
        }
        if (t < cnt) {                        // odd leftover: half 0 only
            int s = __shfl_sync(0xffffffffu, myidx, t);
            if (half == 0) {
                uint2 hv = __ldg(&h8[s * 16 + hl]);
                unsigned f01, f23, f45, f67;
                fp8quad_to_h2(hv.x, f01, f23);
                fp8quad_to_h2(hv.y, f45, f67);
                hacc0 = hadd2f16(hacc0, f01);
                hacc1 = hadd2f16(hacc1, f23);
                hacc2 = hadd2f16(hacc2, f45);
                hacc3 = hadd2f16(hacc3, f67);
            }
        }
    }

    // f16x2 accumulators -> fp32, combine halves
    float a[8];
    h2_to_f32(hacc0, a[0], a[1]);
    h2_to_f32(hacc1, a[2], a[3]);
    h2_to_f32(hacc2, a[4], a[5]);
    h2_to_f32(hacc3, a[6], a[7]);
#pragma unroll
    for (int k = 0; k < 8; k++) a[k] += __shfl_xor_sync(0xffffffffu, a[k], 16);

    if (half == 0) {
        uint4 o;
        o.x = packbf(a[0] * dd, a[1] * dd);
        o.y = packbf(a[2] * dd, a[3] * dd);
        o.z = packbf(a[4] * dd, a[5] * dd);
        o.w = packbf(a[6] * dd, a[7] * dd);
        ((uint4*)g_gb)[node * 16 + hl] = o;
    }
}

// ---------------- K5: persistent bf16 tensor-core GEMM + epilogue -------------
__global__ void __launch_bounds__(256, 4) k_gemm(const float* __restrict__ W2,
                                                 const float* __restrict__ b2,
                                                 const float* __restrict__ Wc,
                                                 const void* batch) {
    extern __shared__ unsigned smu[];
    unsigned* w2t = smu;                 // [128][SB]
    unsigned* gsb = smu + HIDDEN * SB;   // [64][SB]

    int tid = threadIdx.x;
    int w = tid >> 5, lane = tid & 31;
    int is64 = g_is64;

    for (int i = tid; i < HIDDEN * HIDDEN / 8; i += 256) {
        int kp = i >> 5;
        int n4 = (i & 31) << 2;
        float4 a = __ldg((const float4*)&W2[(2 * kp) * HIDDEN + n4]);
        float4 b = __ldg((const float4*)&W2[(2 * kp + 1) * HIDDEN + n4]);
        w2t[(n4 + 0) * SB + kp] = packbf(a.x, b.x);
        w2t[(n4 + 1) * SB + kp] = packbf(a.y, b.y);
        w2t[(n4 + 2) * SB + kp] = packbf(a.z, b.z);
        w2t[(n4 + 3) * SB + kp] = packbf(a.w, b.w);
    }

    int rbase = (w >> 1) * 16;
    int nbase = (w & 1) * 64;
    int fr = lane >> 2;
    int fc = lane & 3;

    for (int tile = blockIdx.x; tile < NTILES; tile += gridDim.x) {
        __syncthreads();
        int base = tile * 64;
        for (int i = tid; i < 1024; i += 256) {
            int r = i >> 4, c4 = i & 15;
            int node = min(base + r, N_NODES - 1);
            uint4 v = __ldg((const uint4*)(g_gb + node * 32) + c4);
            *(uint4*)&gsb[r * SB + c4 * 4] = v;
        }
        __syncthreads();

        const unsigned* ga0 = &gsb[(rbase + fr) * SB];
        const unsigned* ga1 = &gsb[(rbase + fr + 8) * SB];
        float s_lo = 0.f, s_hi = 0.f;

#pragma unroll
        for (int nq = 0; nq < 2; nq++) {
            int nb = nbase + nq * 32;
            float4 acc[4];
#pragma unroll
            for (int n8 = 0; n8 < 4; n8++) {
                float2 bb = __ldg((const float2*)&b2[nb + n8 * 8 + 2 * fc]);
                acc[n8] = make_float4(bb.x, bb.y, bb.x, bb.y);
            }
#pragma unroll
            for (int k16 = 0; k16 < 8; k16++) {
                unsigned a0 = ga0[k16 * 8 + fc];
                unsigned a1 = ga1[k16 * 8 + fc];
                unsigned a2 = ga0[k16 * 8 + fc + 4];
                unsigned a3 = ga1[k16 * 8 + fc + 4];
#pragma unroll
                for (int n8 = 0; n8 < 4; n8++) {
                    const unsigned* wrow = &w2t[(nb + n8 * 8 + fr) * SB];
                    mma_bf16(acc[n8], a0, a1, a2, a3,
                             wrow[k16 * 8 + fc], wrow[k16 * 8 + fc + 4]);
                }
            }
#pragma unroll
            for (int n8 = 0; n8 < 4; n8++) {
                float2 wc = __ldg((const float2*)&Wc[nb + n8 * 8 + 2 * fc]);
                s_lo += fmaxf(acc[n8].x, 0.f) * wc.x + fmaxf(acc[n8].y, 0.f) * wc.y;
                s_hi += fmaxf(acc[n8].z, 0.f) * wc.x + fmaxf(acc[n8].w, 0.f) * wc.y;
            }
        }
#pragma unroll
        for (int off = 1; off <= 2; off <<= 1) {
            s_lo += __shfl_xor_sync(0xffffffffu, s_lo, off);
            s_hi += __shfl_xor_sync(0xffffffffu, s_hi, off);
        }
        if (fc == 0) {
            int node_lo = base + rbase + fr;
            int node_hi = node_lo + 8;
            if (node_lo < N_NODES) {
                int b = is64 ? (int)((const long long*)batch)[node_lo]
                             : ((const int*)batch)[node_lo];
                atomicAdd(&g_gsum[b], s_lo);
            }
            if (node_hi < N_NODES) {
                int b = is64 ? (int)((const long long*)batch)[node_hi]
                             : ((const int*)batch)[node_hi];
                atomicAdd(&g_gsum[b], s_hi);
            }
        }
    }
}

// ---------------- K6: counts via binary search on sorted batch + sigmoid ------
__global__ void k_out(float* __restrict__ out, const float* __restrict__ bc,
                      const void* batch) {
    int g = blockIdx.x * blockDim.x + threadIdx.x;
    if (g >= N_GRAPHS) return;
    int is64 = g_is64;
    int lo = 0, hi = N_NODES;
    while (lo < hi) {               // lower bound of g
        int m = (lo + hi) >> 1;
        int bv = is64 ? (int)((const long long*)batch)[m] : ((const int*)batch)[m];
        if (bv < g) lo = m + 1; else hi = m;
    }
    int lb = lo;
    lo = 0; hi = N_NODES;
    while (lo < hi) {               // upper bound of g
        int m = (lo + hi) >> 1;
        int bv = is64 ? (int)((const long long*)batch)[m] : ((const int*)batch)[m];
        if (bv <= g) lo = m + 1; else hi = m;
    }
    float cnt = fmaxf((float)(lo - lb), 1.0f);
    float logit = g_gsum[g] / cnt + bc[0];
    out[g] = 1.0f / (1.0f + expf(-logit));
}

// ---------------- launch --------------------------------------------------------
extern "C" void kernel_launch(void* const* d_in, const int* in_sizes, int n_in,
                              void* d_out, int out_size) {
    const float* x     = (const float*)d_in[0];
    const void*  ei    = d_in[1];
    const void*  batch = d_in[2];
    const float* W1    = (const float*)d_in[3];
    const float* b1    = (const float*)d_in[4];
    const float* W2    = (const float*)d_in[5];
    const float* b2    = (const float*)d_in[6];
    const float* Wc    = (const float*)d_in[7];
    const float* bc    = (const float*)d_in[8];
    float* out = (float*)d_out;

    const int SMEM = (HIDDEN + 64) * SB * 4;   // 52224 B
    static int smem_set = 0;
    if (!smem_set) {
        cudaFuncSetAttribute(k_gemm, cudaFuncAttributeMaxDynamicSharedMemorySize, SMEM);
        smem_set = 1;
    }

    k_init  <<<(N_NODES + 255) / 256, 256>>>((const unsigned*)ei, x);
    k_fill  <<<(N_EDGES + 255) / 256, 256>>>(ei);
    k_layer1<<<(N_NODES + 63) / 64, 256>>>(W1, b1);
    k_gather<<<(N_NODES + 7) / 8, 256>>>();          // <- profiled slot (#4)
    k_gemm  <<<592, 256, SMEM>>>(W2, b2, Wc, batch);
    k_out   <<<(N_GRAPHS + 255) / 256, 256>>>(out, bc, batch);
}

// round 13
// speedup vs baseline: 1.3028x; 1.1176x over previous
#include <cuda_runtime.h>
#include <cuda_bf16.h>

#define N_NODES  100000
#define N_EDGES  1600000
#define N_GRAPHS 512
#define HIDDEN   128
#define CAP      96        // padded CSR; deg ~ Poisson(16), P(>=96) ~ 1e-45
#define SB       68        // smem row stride in uint32 (64 data + 4 pad)
#define NTILES   ((N_NODES + 63) / 64)

// ---------------- scratch (static device globals) ---------------------------
__device__ float4   g_x4 [N_NODES];          // {x0, x1, x2, (int)count_bits}
__device__ int      g_csr[N_NODES * CAP];    // 38.4 MB padded CSR
__device__ unsigned g_h8 [N_NODES * 32];     // h' rows e4m3, 128 B/row (12.8 MB)
__device__ unsigned g_y8 [N_NODES * 32];     // Y = h'@W2 rows e4m3 (12.8 MB)
__device__ float    g_gsum[N_GRAPHS];
__device__ int      g_is64;

// ---------------- helpers ----------------------------------------------------
__device__ __forceinline__ unsigned packbf(float lo, float hi) {
    __nv_bfloat162 p = __float22bfloat162_rn(make_float2(lo, hi));
    return *(const unsigned*)&p;
}
// 4 fp32 -> 4 e4m3 packed in a u32 (y0 in lowest byte)
__device__ __forceinline__ unsigned pack_e4m3_4(float y0, float y1, float y2, float y3) {
    unsigned short lo, hi;
    asm("cvt.rn.satfinite.e4m3x2.f32 %0, %1, %2;" : "=h"(lo) : "f"(y1), "f"(y0));
    asm("cvt.rn.satfinite.e4m3x2.f32 %0, %1, %2;" : "=h"(hi) : "f"(y3), "f"(y2));
    unsigned r;
    asm("mov.b32 %0, {%1,%2};" : "=r"(r) : "h"(lo), "h"(hi));
    return r;
}
// 2 fp32 -> u16 of 2 e4m3 (c0 in low byte)
__device__ __forceinline__ unsigned short pack_e4m3_2(float c0, float c1) {
    unsigned short r;
    asm("cvt.rn.satfinite.e4m3x2.f32 %0, %1, %2;" : "=h"(r) : "f"(c1), "f"(c0));
    return r;
}
// u32 of 4 e4m3 -> two f16x2 (exact widening)
__device__ __forceinline__ void fp8quad_to_h2(unsigned w, unsigned& f01, unsigned& f23) {
    unsigned short l, h;
    asm("mov.b32 {%0,%1}, %2;" : "=h"(l), "=h"(h) : "r"(w));
    asm("cvt.rn.f16x2.e4m3x2 %0, %1;" : "=r"(f01) : "h"(l));
    asm("cvt.rn.f16x2.e4m3x2 %0, %1;" : "=r"(f23) : "h"(h));
}
__device__ __forceinline__ unsigned hadd2f16(unsigned a, unsigned b) {
    unsigned r; asm("add.rn.f16x2 %0, %1, %2;" : "=r"(r) : "r"(a), "r"(b)); return r;
}
__device__ __forceinline__ void h2_to_f32(unsigned p, float& lo, float& hi) {
    unsigned short l, h;
    asm("mov.b32 {%0,%1}, %2;" : "=h"(l), "=h"(h) : "r"(p));
    asm("cvt.f32.f16 %0, %1;" : "=f"(lo) : "h"(l));
    asm("cvt.f32.f16 %0, %1;" : "=f"(hi) : "h"(h));
}
__device__ __forceinline__ void mma_bf16(float4& d, unsigned a0, unsigned a1,
                                         unsigned a2, unsigned a3,
                                         unsigned b0, unsigned b1) {
    asm("mma.sync.aligned.m16n8k16.row.col.f32.bf16.bf16.f32 "
        "{%0,%1,%2,%3}, {%4,%5,%6,%7}, {%8,%9}, {%0,%1,%2,%3};"
        : "+f"(d.x), "+f"(d.y), "+f"(d.z), "+f"(d.w)
        : "r"(a0), "r"(a1), "r"(a2), "r"(a3), "r"(b0), "r"(b1));
}

// ---------------- K1: init (x4 count=0, gsum, dtype detect) -------------------
__global__ void k_init(const unsigned* __restrict__ ei, const float* __restrict__ x) {
    int i = blockIdx.x * blockDim.x + threadIdx.x;
    if (i == 0) {
        unsigned orv = 0;
#pragma unroll
        for (int t = 1; t < 32; t += 2) orv |= ei[t];   // int64 => high words zero
        g_is64 = (orv == 0u) ? 1 : 0;
    }
    if (i < N_NODES)
        g_x4[i] = make_float4(x[3 * i], x[3 * i + 1], x[3 * i + 2], 0.0f);
    if (i < N_GRAPHS) g_gsum[i] = 0.0f;
}

// ---------------- K2: build padded CSR; counter lives in g_x4[d].w ------------
__global__ void __launch_bounds__(256) k_fill(const void* ei) {
    int e = blockIdx.x * blockDim.x + threadIdx.x;
    if (e >= N_EDGES) return;
    int s, d;
    if (g_is64) {
        s = (int)((const long long*)ei)[e];
        d = (int)((const long long*)ei)[(long long)N_EDGES + e];
    } else {
        s = ((const int*)ei)[e];
        d = ((const int*)ei)[N_EDGES + e];
    }
    int slot = atomicAdd((int*)&g_x4[d].w, 1);
    if (slot < CAP) g_csr[d * CAP + slot] = s;
}

// ---------------- K3: fused layer 1 (inline neighbor dinv -> fp8 h') ----------
__global__ void __launch_bounds__(256) k_layer1(const float* __restrict__ W1,
                                                const float* __restrict__ b1) {
    int w = threadIdx.x >> 5, lane = threadIdx.x & 31;
    int g = lane >> 2, q = lane & 3;
    int nodeBase = blockIdx.x * 64 + w * 8;
    int nc = min(nodeBase + g, N_NODES - 1);
    float4 xs = g_x4[nc];
    int cr    = __float_as_int(xs.w);
    int deg   = min(cr, CAP);
    float dd  = rsqrtf((float)(cr + 1));
    int start = nc * CAP;

    float px = 0.f, py = 0.f, pz = 0.f;
    for (int j = q; j < deg; j += 4) {
        int s = g_csr[start + j];
        float4 v = __ldg(&g_x4[s]);
        float ds = rsqrtf((float)(__float_as_int(v.w) + 1));
        px = fmaf(v.x, ds, px);
        py = fmaf(v.y, ds, py);
        pz = fmaf(v.z, ds, pz);
    }
#pragma unroll
    for (int off = 1; off <= 2; off <<= 1) {
        px += __shfl_xor_sync(0xffffffffu, px, off);
        py += __shfl_xor_sync(0xffffffffu, py, off);
        pz += __shfl_xor_sync(0xffffffffu, pz, off);
    }
    float v0 = dd * (px + xs.x * dd);
    float v1 = dd * (py + xs.y * dd);
    float v2 = dd * (pz + xs.z * dd);

    int c0 = lane << 2;
    const float4 w0 = *(const float4*)&W1[c0];
    const float4 w1 = *(const float4*)&W1[HIDDEN + c0];
    const float4 w2 = *(const float4*)&W1[2 * HIDDEN + c0];
    const float4 bb = *(const float4*)&b1[c0];

#pragma unroll
    for (int r = 0; r < 8; r++) {
        float u0 = __shfl_sync(0xffffffffu, v0, r * 4);
        float u1 = __shfl_sync(0xffffffffu, v1, r * 4);
        float u2 = __shfl_sync(0xffffffffu, v2, r * 4);
        float ud = __shfl_sync(0xffffffffu, dd, r * 4);
        int nd = nodeBase + r;
        if (nd >= N_NODES) break;
        float y0 = fmaf(u0, w0.x, fmaf(u1, w1.x, fmaf(u2, w2.x, bb.x)));
        float y1 = fmaf(u0, w0.y, fmaf(u1, w1.y, fmaf(u2, w2.y, bb.y)));
        float y2 = fmaf(u0, w0.z, fmaf(u1, w1.z, fmaf(u2, w2.z, bb.z)));
        float y3 = fmaf(u0, w0.w, fmaf(u1, w1.w, fmaf(u2, w2.w, bb.w)));
        y0 = fmaxf(y0, 0.f) * ud; y1 = fmaxf(y1, 0.f) * ud;
        y2 = fmaxf(y2, 0.f) * ud; y3 = fmaxf(y3, 0.f) * ud;
        g_h8[nd * 32 + lane] = pack_e4m3_4(y0, y1, y2, y3);   // 128B coalesced row
    }
}

// ---------------- K4: dense Y = H @ W2 (persistent bf16 MMA, fp8 in/out) ------
// smem u32: w2t[128][SB] | gsb[64][SB] | yo[2048] (fp8 out staging) = 60416 B
__global__ void __launch_bounds__(256) k_y(const float* __restrict__ W2) {
    extern __shared__ unsigned smu[];
    unsigned* w2t = smu;                       // [128][SB]
    unsigned* gsb = smu + HIDDEN * SB;         // [64][SB] bf16 A tile
    unsigned* yo  = smu + (HIDDEN + 64) * SB;  // [2048] fp8 out tile (8 KB)

    int tid = threadIdx.x;
    int w = tid >> 5, lane = tid & 31;

    // stage W2 transposed as bf16 k-pairs (once)
    for (int i = tid; i < HIDDEN * HIDDEN / 8; i += 256) {
        int kp = i >> 5;
        int n4 = (i & 31) << 2;
        float4 a = __ldg((const float4*)&W2[(2 * kp) * HIDDEN + n4]);
        float4 b = __ldg((const float4*)&W2[(2 * kp + 1) * HIDDEN + n4]);
        w2t[(n4 + 0) * SB + kp] = packbf(a.x, b.x);
        w2t[(n4 + 1) * SB + kp] = packbf(a.y, b.y);
        w2t[(n4 + 2) * SB + kp] = packbf(a.z, b.z);
        w2t[(n4 + 3) * SB + kp] = packbf(a.w, b.w);
    }

    int rbase = (w >> 1) * 16;
    int nbase = (w & 1) * 64;
    int fr = lane >> 2;
    int fc = lane & 3;

    for (int tile = blockIdx.x; tile < NTILES; tile += gridDim.x) {
        __syncthreads();   // w2t ready / prev copy-out done
        int base = tile * 64;
        // load H tile fp8 -> bf16 smem (coalesced)
        for (int i = tid; i < 2048; i += 256) {
            int r = i >> 5, c = i & 31;
            int node = min(base + r, N_NODES - 1);
            unsigned v = __ldg(&g_h8[node * 32 + c]);
            unsigned f01, f23;
            fp8quad_to_h2(v, f01, f23);
            float lo, hi;
            h2_to_f32(f01, lo, hi); gsb[r * SB + 2 * c]     = packbf(lo, hi);
            h2_to_f32(f23, lo, hi); gsb[r * SB + 2 * c + 1] = packbf(lo, hi);
        }
        __syncthreads();

        const unsigned* ga0 = &gsb[(rbase + fr) * SB];
        const unsigned* ga1 = &gsb[(rbase + fr + 8) * SB];
        unsigned short* yo16 = (unsigned short*)yo;

#pragma unroll
        for (int nq = 0; nq < 2; nq++) {
            int nb = nbase + nq * 32;
            float4 acc[4];
#pragma unroll
            for (int n8 = 0; n8 < 4; n8++) acc[n8] = make_float4(0.f, 0.f, 0.f, 0.f);
#pragma unroll
            for (int k16 = 0; k16 < 8; k16++) {
                unsigned a0 = ga0[k16 * 8 + fc];
                unsigned a1 = ga1[k16 * 8 + fc];
                unsigned a2 = ga0[k16 * 8 + fc + 4];
                unsigned a3 = ga1[k16 * 8 + fc + 4];
#pragma unroll
                for (int n8 = 0; n8 < 4; n8++) {
                    const unsigned* wrow = &w2t[(nb + n8 * 8 + fr) * SB];
                    mma_bf16(acc[n8], a0, a1, a2, a3,
                             wrow[k16 * 8 + fc], wrow[k16 * 8 + fc + 4]);
                }
            }
            // stash fp8 pairs into out staging (own data only; no race)
#pragma unroll
            for (int n8 = 0; n8 < 4; n8++) {
                int cidx = (nb + n8 * 8) >> 1;   // u16 col-pair index
                yo16[(rbase + fr) * 64 + cidx + fc]     = pack_e4m3_2(acc[n8].x, acc[n8].y);
                yo16[(rbase + fr + 8) * 64 + cidx + fc] = pack_e4m3_2(acc[n8].z, acc[n8].w);
            }
        }
        __syncthreads();
        // coalesced copy out: 64 rows x 128 B
        for (int i = tid; i < 512; i += 256) {
            int r = i >> 3, c4 = i & 7;
            int node = base + r;
            if (node < N_NODES)
                *((uint4*)g_y8 + node * 8 + c4) = ((const uint4*)yo)[i];
        }
    }
}

// ---------------- K5: gather Y rows + FINAL epilogue (relu/Wc/pool) -----------
// 2 edges/warp: 16 lanes per row, uint2 (8B = 8 fp8 cols) per lane.
__global__ void __launch_bounds__(256) k_gather(const float* __restrict__ b2,
                                                const float* __restrict__ Wc,
                                                const void* batch) {
    int w = threadIdx.x >> 5, lane = threadIdx.x & 31;
    int node = blockIdx.x * 8 + w;
    if (node >= N_NODES) return;
    int cr    = __float_as_int(g_x4[node].w);
    int deg   = min(cr, CAP);
    float dd  = rsqrtf((float)(cr + 1));
    int start = node * CAP;
    int half = lane >> 4;
    int hl   = lane & 15;

    const uint2* y8 = (const uint2*)g_y8;    // 16 uint2 per 128B row

    unsigned hacc0 = 0u, hacc1 = 0u, hacc2 = 0u, hacc3 = 0u;   // f16x2 accums
    if (half == 0) {                          // self term once
        uint2 sv = __ldg(&y8[node * 16 + hl]);
        fp8quad_to_h2(sv.x, hacc0, hacc1);
        fp8quad_to_h2(sv.y, hacc2, hacc3);
    }

    for (int jb = 0; jb < deg; jb += 32) {
        int j = jb + lane;
        int myidx = (j < deg) ? g_csr[start + j] : 0;
        int cnt = min(32, deg - jb);
        int t = 0;
        for (; t + 8 <= cnt; t += 8) {        // 4 row-loads in flight per lane
            uint2 h[4];
#pragma unroll
            for (int u = 0; u < 4; u++) {
                int s = __shfl_sync(0xffffffffu, myidx, t + 2 * u + half);
                h[u] = __ldg(&y8[s * 16 + hl]);
            }
            unsigned a01, a23, a45, a67, b01, b23, b45, b67;
            fp8quad_to_h2(h[0].x, a01, a23); fp8quad_to_h2(h[0].y, a45, a67);
            fp8quad_to_h2(h[1].x, b01, b23); fp8quad_to_h2(h[1].y, b45, b67);
            hacc0 = hadd2f16(hacc0, hadd2f16(a01, b01));
            hacc1 = hadd2f16(hacc1, hadd2f16(a23, b23));
            hacc2 = hadd2f16(hacc2, hadd2f16(a45, b45));
            hacc3 = hadd2f16(hacc3, hadd2f16(a67, b67));
            fp8quad_to_h2(h[2].x, a01, a23); fp8quad_to_h2(h[2].y, a45, a67);
            fp8quad_to_h2(h[3].x, b01, b23); fp8quad_to_h2(h[3].y, b45, b67);
            hacc0 = hadd2f16(hacc0, hadd2f16(a01, b01));
            hacc1 = hadd2f16(hacc1, hadd2f16(a23, b23));
            hacc2 = hadd2f16(hacc2, hadd2f16(a45, b45));
            hacc3 = hadd2f16(hacc3, hadd2f16(a67, b67));
        }
        for (; t + 2 <= cnt; t += 2) {
            int s = __shfl_sync(0xffffffffu, myidx, t + half);
            uint2 hv = __ldg(&y8[s * 16 + hl]);
            unsigned f01, f23, f45, f67;
            fp8quad_to_h2(hv.x, f01, f23);
            fp8quad_to_h2(hv.y, f45, f67);
            hacc0 = hadd2f16(hacc0, f01);
            hacc1 = hadd2f16(hacc1, f23);
            hacc2 = hadd2f16(hacc2, f45);
            hacc3 = hadd2f16(hacc3, f67);
        }
        if (t < cnt) {                        // odd leftover: half 0 only
            int s = __shfl_sync(0xffffffffu, myidx, t);
            if (half == 0) {
                uint2 hv = __ldg(&y8[s * 16 + hl]);
                unsigned f01, f23, f45, f67;
                fp8quad_to_h2(hv.x, f01, f23);
                fp8quad_to_h2(hv.y, f45, f67);
                hacc0 = hadd2f16(hacc0, f01);
                hacc1 = hadd2f16(hacc1, f23);
                hacc2 = hadd2f16(hacc2, f45);
                hacc3 = hadd2f16(hacc3, f67);
            }
        }
    }

    // f16x2 accumulators -> fp32, combine halves (both halves get the sum)
    float a[8];
    h2_to_f32(hacc0, a[0], a[1]);
    h2_to_f32(hacc1, a[2], a[3]);
    h2_to_f32(hacc2, a[4], a[5]);
    h2_to_f32(hacc3, a[6], a[7]);
#pragma unroll
    for (int k = 0; k < 8; k++) a[k] += __shfl_xor_sync(0xffffffffu, a[k], 16);

    // FINAL epilogue: relu(dd*sumY + b2) . Wc  over this lane's 8 cols
    int c0 = hl << 3;
    const float4 b2a = __ldg((const float4*)&b2[c0]);
    const float4 b2b = __ldg((const float4*)&b2[c0 + 4]);
    const float4 wca = __ldg((const float4*)&Wc[c0]);
    const float4 wcb = __ldg((const float4*)&Wc[c0 + 4]);
    float p = fmaxf(fmaf(dd, a[0], b2a.x), 0.f) * wca.x
            + fmaxf(fmaf(dd, a[1], b2a.y), 0.f) * wca.y
            + fmaxf(fmaf(dd, a[2], b2a.z), 0.f) * wca.z
            + fmaxf(fmaf(dd, a[3], b2a.w), 0.f) * wca.w
            + fmaxf(fmaf(dd, a[4], b2b.x), 0.f) * wcb.x
            + fmaxf(fmaf(dd, a[5], b2b.y), 0.f) * wcb.y
            + fmaxf(fmaf(dd, a[6], b2b.z), 0.f) * wcb.z
            + fmaxf(fmaf(dd, a[7], b2b.w), 0.f) * wcb.w;
#pragma unroll
    for (int off = 1; off <= 8; off <<= 1)     // reduce over the 16-lane group
        p += __shfl_xor_sync(0xffffffffu, p, off);
    if (lane == 0) {
        int b = g_is64 ? (int)((const long long*)batch)[node]
                       : ((const int*)batch)[node];
        atomicAdd(&g_gsum[b], p);
    }
}

// ---------------- K6: counts via binary search on sorted batch + sigmoid ------
__global__ void k_out(float* __restrict__ out, const float* __restrict__ bc,
                      const void* batch) {
    int g = blockIdx.x * blockDim.x + threadIdx.x;
    if (g >= N_GRAPHS) return;
    int is64 = g_is64;
    int lo = 0, hi = N_NODES;
    while (lo < hi) {               // lower bound of g
        int m = (lo + hi) >> 1;
        int bv = is64 ? (int)((const long long*)batch)[m] : ((const int*)batch)[m];
        if (bv < g) lo = m + 1; else hi = m;
    }
    int lb = lo;
    lo = 0; hi = N_NODES;
    while (lo < hi) {               // upper bound of g
        int m = (lo + hi) >> 1;
        int bv = is64 ? (int)((const long long*)batch)[m] : ((const int*)batch)[m];
        if (bv <= g) lo = m + 1; else hi = m;
    }
    float cnt = fmaxf((float)(lo - lb), 1.0f);
    float logit = g_gsum[g] / cnt + bc[0];
    out[g] = 1.0f / (1.0f + expf(-logit));
}

// ---------------- launch --------------------------------------------------------
extern "C" void kernel_launch(void* const* d_in, const int* in_sizes, int n_in,
                              void* d_out, int out_size) {
    const float* x     = (const float*)d_in[0];
    const void*  ei    = d_in[1];
    const void*  batch = d_in[2];
    const float* W1    = (const float*)d_in[3];
    const float* b1    = (const float*)d_in[4];
    const float* W2    = (const float*)d_in[5];
    const float* b2    = (const float*)d_in[6];
    const float* Wc    = (const float*)d_in[7];
    const float* bc    = (const float*)d_in[8];
    float* out = (float*)d_out;

    const int SMEM_Y = (HIDDEN + 64) * SB * 4 + 2048 * 4;   // 60416 B
    static int smem_set = 0;
    if (!smem_set) {
        cudaFuncSetAttribute(k_y, cudaFuncAttributeMaxDynamicSharedMemorySize, SMEM_Y);
        smem_set = 1;
    }

    k_init  <<<(N_NODES + 255) / 256, 256>>>((const unsigned*)ei, x);
    k_fill  <<<(N_EDGES + 255) / 256, 256>>>(ei);
    k_layer1<<<(N_NODES + 63) / 64, 256>>>(W1, b1);
    k_y     <<<444, 256, SMEM_Y>>>(W2);              // <- profiled slot (#4)
    k_gather<<<(N_NODES + 7) / 8, 256>>>(b2, Wc, batch);
    k_out   <<<(N_GRAPHS + 255) / 256, 256>>>(out, bc, batch);
}